// round 2
// baseline (speedup 1.0000x reference)
#include <cuda_runtime.h>

#define NB  32
#define IDF 768
#define CDF 768
#define QL  1024
#define SL  128

// Scratch for the projected context sourceT[b][o][s]  (12.6 MB)
__device__ float g_srcT[(size_t)NB * IDF * SL];

// ---------------------------------------------------------------------------
// Kernel A: sourceT[b,o,s] = sum_c w[o,c] * ctx[b,c,s]
// One block per (o-tile of 128, b). 256 threads, 8x8 register tile, BK=16.
// ---------------------------------------------------------------------------
__global__ void __launch_bounds__(256, 1) proj_kernel(const float* __restrict__ w,
                                                      const float* __restrict__ ctx) {
    __shared__ float As[16 * 128];   // [c][o]  (transposed on store)
    __shared__ float Bs[16 * 128];   // [c][s]
    const int b  = blockIdx.y;
    const int o0 = blockIdx.x * 128;
    const int tid = threadIdx.x;
    const int tx = tid & 15, ty = tid >> 4;
    const float* ctxb = ctx + (size_t)b * CDF * SL;

    float acc[8][8];
#pragma unroll
    for (int i = 0; i < 8; i++)
#pragma unroll
        for (int j = 0; j < 8; j++) acc[i][j] = 0.f;

    for (int c0 = 0; c0 < CDF; c0 += 16) {
#pragma unroll
        for (int l = 0; l < 2; l++) {
            int li = tid * 2 + l;                 // 0..511 (float4 index)
            // A: w tile 128(o) x 16(c), transpose into As[c][o]
            int row = li >> 2;                    // o 0..127
            int col = (li & 3) * 4;               // c 0..12
            float4 v = *(const float4*)(w + (size_t)(o0 + row) * CDF + c0 + col);
            As[(col + 0) * 128 + row] = v.x;
            As[(col + 1) * 128 + row] = v.y;
            As[(col + 2) * 128 + row] = v.z;
            As[(col + 3) * 128 + row] = v.w;
            // B: ctx tile 16(c) x 128(s), direct
            int brow = li >> 5;                   // c 0..15
            int bcol = (li & 31) * 4;             // s
            *(float4*)(Bs + brow * 128 + bcol) =
                *(const float4*)(ctxb + (size_t)(c0 + brow) * SL + bcol);
        }
        __syncthreads();
#pragma unroll
        for (int k = 0; k < 16; k++) {
            float a[8], bb[8];
            *(float4*)(a)      = *(const float4*)(As + k * 128 + ty * 8);
            *(float4*)(a + 4)  = *(const float4*)(As + k * 128 + ty * 8 + 4);
            *(float4*)(bb)     = *(const float4*)(Bs + k * 128 + tx * 8);
            *(float4*)(bb + 4) = *(const float4*)(Bs + k * 128 + tx * 8 + 4);
#pragma unroll
            for (int i = 0; i < 8; i++)
#pragma unroll
                for (int j = 0; j < 8; j++)
                    acc[i][j] = fmaf(a[i], bb[j], acc[i][j]);
        }
        __syncthreads();
    }

    float* outb = g_srcT + ((size_t)b * IDF + o0) * SL;
#pragma unroll
    for (int i = 0; i < 8; i++)
#pragma unroll
        for (int j = 0; j < 8; j += 4)
            *(float4*)(outb + (size_t)(ty * 8 + i) * SL + tx * 8 + j) = *(float4*)(&acc[i][j]);
}

// ---------------------------------------------------------------------------
// Kernel B: fused attention per (b, q-tile of 128).
//  phase 1: logits[q][s] = sum_i target[i][q] * srcT[i][s]   (K=768)
//  phase 2: + mask*(-1e4), softmax over s, store TRANSPOSED attnT[s][q]
//           (attnT layout == attn_out layout; also k-major for phase 3)
//  phase 3: wc[i][q] = sum_s srcT[i][s] * attnT[s][q]        (6 chunks of 128 i)
// ---------------------------------------------------------------------------
__global__ void __launch_bounds__(256, 1) attn_kernel(const float* __restrict__ tgt_all,
                                                      const int* __restrict__ mask,
                                                      float* __restrict__ wc,
                                                      float* __restrict__ aout) {
    extern __shared__ float smem[];
    float* attnT = smem;               // [128 s][128 q], stride 128
    float* sTT   = smem + 128 * 128;   // [128 s][128 i], stride 129 (phase 3)
    float* As    = sTT;                // phase-1 alias: [16 k][128 q]
    float* Bs    = sTT + 16 * 128;     // phase-1 alias: [16 k][128 s]
    __shared__ int maskS[SL];

    const int b  = blockIdx.y;
    const int q0 = blockIdx.x * 128;
    const int tid = threadIdx.x;
    const int tx = tid & 15, ty = tid >> 4;
    const float* tgt = tgt_all + (size_t)b * IDF * QL;   // [i][q]
    const float* sT  = g_srcT  + (size_t)b * IDF * SL;   // [i][s]

    if (tid < SL) maskS[tid] = mask[b * SL + tid];

    // ---- phase 1: logits, rows q = ty*8+i, cols s = tx*8+j ----
    float acc[8][8];
#pragma unroll
    for (int i = 0; i < 8; i++)
#pragma unroll
        for (int j = 0; j < 8; j++) acc[i][j] = 0.f;

    for (int k0 = 0; k0 < IDF; k0 += 16) {
#pragma unroll
        for (int l = 0; l < 2; l++) {
            int li  = tid * 2 + l;        // 0..511
            int row = li >> 5;            // k 0..15
            int col = (li & 31) * 4;
            *(float4*)(As + row * 128 + col) =
                *(const float4*)(tgt + (size_t)(k0 + row) * QL + q0 + col);
            *(float4*)(Bs + row * 128 + col) =
                *(const float4*)(sT + (size_t)(k0 + row) * SL + col);
        }
        __syncthreads();
#pragma unroll
        for (int k = 0; k < 16; k++) {
            float a[8], bb[8];
            *(float4*)(a)      = *(const float4*)(As + k * 128 + ty * 8);
            *(float4*)(a + 4)  = *(const float4*)(As + k * 128 + ty * 8 + 4);
            *(float4*)(bb)     = *(const float4*)(Bs + k * 128 + tx * 8);
            *(float4*)(bb + 4) = *(const float4*)(Bs + k * 128 + tx * 8 + 4);
#pragma unroll
            for (int i = 0; i < 8; i++)
#pragma unroll
                for (int j = 0; j < 8; j++)
                    acc[i][j] = fmaf(a[i], bb[j], acc[i][j]);
        }
        __syncthreads();
    }

    // ---- phase 2: mask + transposed store + softmax over s ----
#pragma unroll
    for (int j = 0; j < 8; j++) {
        int s = tx * 8 + j;
        float mpen = -10000.0f * (float)maskS[s];
#pragma unroll
        for (int i = 0; i < 8; i++)
            attnT[s * 128 + ty * 8 + i] = acc[i][j] + mpen;
    }
    __syncthreads();

    {
        int q = tid >> 1;          // each column handled by 2 adjacent threads
        int h = tid & 1;
        float mx = -1e30f;
        for (int j = 0; j < 64; j++)
            mx = fmaxf(mx, attnT[(h * 64 + j) * 128 + q]);
        mx = fmaxf(mx, __shfl_xor_sync(0xffffffffu, mx, 1));
        float sum = 0.f;
        for (int j = 0; j < 64; j++) {
            int idx = (h * 64 + j) * 128 + q;
            float e = __expf(attnT[idx] - mx);
            attnT[idx] = e;
            sum += e;
        }
        sum += __shfl_xor_sync(0xffffffffu, sum, 1);
        float inv = 1.0f / sum;
        for (int j = 0; j < 64; j++)
            attnT[(h * 64 + j) * 128 + q] *= inv;
    }
    __syncthreads();

    // ---- attn_out[b][s][q0+q] = attnT[s][q] (already transposed) ----
    {
        float* ao = aout + (size_t)b * SL * QL + q0;
        for (int li = tid; li < 128 * 32; li += 256) {
            int s = li >> 5;
            int c = (li & 31) * 4;
            *(float4*)(ao + (size_t)s * QL + c) = *(const float4*)(attnT + s * 128 + c);
        }
    }

    // ---- phase 3: wc, 6 chunks of 128 i ----
    float* wcb = wc + (size_t)b * IDF * QL + q0;
    for (int i0 = 0; i0 < IDF; i0 += 128) {
        __syncthreads();   // prior sTT readers done (also first iter: attn_out writers)
        // sTT[s][i] = sT[i0+i][s], stride 129 avoids broadcast-row conflicts
        for (int li = tid; li < 128 * 32; li += 256) {
            int i = li >> 5;
            int c = (li & 31) * 4;
            float4 v = *(const float4*)(sT + (size_t)(i0 + i) * SL + c);
            sTT[(c + 0) * 129 + i] = v.x;
            sTT[(c + 1) * 129 + i] = v.y;
            sTT[(c + 2) * 129 + i] = v.z;
            sTT[(c + 3) * 129 + i] = v.w;
        }
        __syncthreads();

        float c8[8][8];
#pragma unroll
        for (int m = 0; m < 8; m++)
#pragma unroll
            for (int n = 0; n < 8; n++) c8[m][n] = 0.f;

#pragma unroll 4
        for (int k = 0; k < 128; k++) {
            float a[8], bb[8];
#pragma unroll
            for (int m = 0; m < 8; m++) a[m] = sTT[k * 129 + ty * 8 + m];
            *(float4*)(bb)     = *(const float4*)(attnT + k * 128 + tx * 8);
            *(float4*)(bb + 4) = *(const float4*)(attnT + k * 128 + tx * 8 + 4);
#pragma unroll
            for (int m = 0; m < 8; m++)
#pragma unroll
                for (int n = 0; n < 8; n++)
                    c8[m][n] = fmaf(a[m], bb[n], c8[m][n]);
        }
#pragma unroll
        for (int m = 0; m < 8; m++)
#pragma unroll
            for (int n = 0; n < 8; n += 4)
                *(float4*)(wcb + (size_t)(i0 + ty * 8 + m) * QL + tx * 8 + n) =
                    *(float4*)(&c8[m][n]);
    }
}

// ---------------------------------------------------------------------------
extern "C" void kernel_launch(void* const* d_in, const int* in_sizes, int n_in,
                              void* d_out, int out_size) {
    const float* input   = (const float*)d_in[0];   // [32,768,32,32]
    const float* context = (const float*)d_in[1];   // [32,768,128]
    const int*   mask    = (const int*)d_in[2];     // [32,128]
    const float* w_conv  = (const float*)d_in[3];   // [768,768]

    float* wc   = (float*)d_out;                    // [32,768,1024]
    float* aout = wc + (size_t)NB * IDF * QL;       // [32,128,1024]

    proj_kernel<<<dim3(IDF / 128, NB), 256>>>(w_conv, context);

    const size_t smem_b = (size_t)(128 * 128 + 128 * 129) * sizeof(float); // 131584
    cudaFuncSetAttribute(attn_kernel, cudaFuncAttributeMaxDynamicSharedMemorySize,
                         (int)smem_b);
    attn_kernel<<<dim3(QL / 128, NB), 256, smem_b>>>(input, mask, wc, aout);
}

// round 4
// speedup vs baseline: 1.8117x; 1.8117x over previous
#include <cuda_runtime.h>
#include <cuda_bf16.h>
#include <stdint.h>

#define NB  32
#define IDF 768
#define CDF 768
#define QL  1024
#define SL  128

__device__ __align__(128) __nv_bfloat16 g_w_hi[(size_t)IDF * CDF];
__device__ __align__(128) __nv_bfloat16 g_w_lo[(size_t)IDF * CDF];
__device__ __align__(128) __nv_bfloat16 g_ctxT_hi[(size_t)NB * SL * CDF];
__device__ __align__(128) __nv_bfloat16 g_ctxT_lo[(size_t)NB * SL * CDF];
__device__ __align__(128) __nv_bfloat16 g_tgtT_hi[(size_t)NB * QL * IDF];
__device__ __align__(128) __nv_bfloat16 g_tgtT_lo[(size_t)NB * QL * IDF];
__device__ __align__(128) __nv_bfloat16 g_sis_hi[(size_t)NB * IDF * SL];
__device__ __align__(128) __nv_bfloat16 g_sis_lo[(size_t)NB * IDF * SL];
__device__ __align__(128) __nv_bfloat16 g_ssi_hi[(size_t)NB * SL * IDF];
__device__ __align__(128) __nv_bfloat16 g_ssi_lo[(size_t)NB * SL * IDF];

__device__ __forceinline__ uint32_t smem_u32(const void* p) {
    uint32_t a;
    asm("{ .reg .u64 t; cvta.to.shared.u64 t, %1; cvt.u32.u64 %0, t; }" : "=r"(a) : "l"(p));
    return a;
}
#define SW128(x) ((x) ^ (((x) >> 3) & 0x70))

__device__ __forceinline__ void split2(float v, __nv_bfloat16& h, __nv_bfloat16& l) {
    h = __float2bfloat16(v);
    l = __float2bfloat16(v - __bfloat162float(h));
}
__device__ __forceinline__ uint32_t pack_bf2(__nv_bfloat16 a, __nv_bfloat16 b) {
    __nv_bfloat162 p; p.x = a; p.y = b;
    return *reinterpret_cast<uint32_t*>(&p);
}

// [128 rows x 128 bytes] bf16 K-major tile, SW128-swizzled into smem. gstride bytes.
__device__ __forceinline__ void cp_tile(uint32_t sbase, const __nv_bfloat16* g,
                                        int gstride, int tid) {
#pragma unroll
    for (int p = 0; p < 4; p++) {
        int idx = tid + p * 256;
        int row = idx >> 3;
        int c   = (idx & 7) << 4;
        const uint4 v = *reinterpret_cast<const uint4*>(
            reinterpret_cast<const char*>(g) + (size_t)row * gstride + c);
        uint32_t so = sbase + SW128((uint32_t)(row * 128 + c));
        asm volatile("st.shared.v4.b32 [%0], {%1,%2,%3,%4};"
                     :: "r"(so), "r"(v.x), "r"(v.y), "r"(v.z), "r"(v.w));
    }
}

// x4 ldmatrix of a 16x16 bf16 block at (row0, kbyte) in a SW128 [r][128B] tile.
__device__ __forceinline__ void ldm4(uint32_t r[4], uint32_t base, int row0,
                                     int kbyte, int lane) {
    int row = row0 + (lane & 15);
    int col = kbyte + ((lane >> 4) << 4);
    uint32_t addr = base + SW128((uint32_t)(row * 128 + col));
    asm volatile("ldmatrix.sync.aligned.m8n8.x4.shared.b16 {%0,%1,%2,%3}, [%4];"
                 : "=r"(r[0]), "=r"(r[1]), "=r"(r[2]), "=r"(r[3]) : "r"(addr));
}

__device__ __forceinline__ void mma16(float c[4], const uint32_t a[4], const uint32_t b[2]) {
    asm volatile("mma.sync.aligned.m16n8k16.row.col.f32.bf16.bf16.f32 "
                 "{%0,%1,%2,%3}, {%4,%5,%6,%7}, {%8,%9}, {%0,%1,%2,%3};"
                 : "+f"(c[0]), "+f"(c[1]), "+f"(c[2]), "+f"(c[3])
                 : "r"(a[0]), "r"(a[1]), "r"(a[2]), "r"(a[3]), "r"(b[0]), "r"(b[1]));
}

// One k16 step of the 32(m) x 64(n) warp tile with split-bf16 (3 mmas/pair).
__device__ __forceinline__ void gemm_k16(float acc[2][8][4],
                                         uint32_t aHi, uint32_t aLo,
                                         uint32_t bHi, uint32_t bLo,
                                         int kbyte, int m0, int n0, int lane) {
    uint32_t ah[2][4], al[2][4], bh[8][2], bl[8][2];
#pragma unroll
    for (int m = 0; m < 2; m++) {
        ldm4(ah[m], aHi, m0 + m * 16, kbyte, lane);
        ldm4(al[m], aLo, m0 + m * 16, kbyte, lane);
    }
#pragma unroll
    for (int j = 0; j < 4; j++) {
        uint32_t t[4];
        ldm4(t, bHi, n0 + j * 16, kbyte, lane);
        bh[2 * j][0] = t[0]; bh[2 * j][1] = t[2];
        bh[2 * j + 1][0] = t[1]; bh[2 * j + 1][1] = t[3];
        ldm4(t, bLo, n0 + j * 16, kbyte, lane);
        bl[2 * j][0] = t[0]; bl[2 * j][1] = t[2];
        bl[2 * j + 1][0] = t[1]; bl[2 * j + 1][1] = t[3];
    }
#pragma unroll
    for (int m = 0; m < 2; m++)
#pragma unroll
        for (int n = 0; n < 8; n++) {
            mma16(acc[m][n], ah[m], bh[n]);
            mma16(acc[m][n], ah[m], bl[n]);
            mma16(acc[m][n], al[m], bh[n]);
        }
}

__device__ __forceinline__ void frag_to_cbuf(float* Cb, const float acc[2][8][4],
                                             int m0, int n0, int lane) {
#pragma unroll
    for (int m = 0; m < 2; m++)
#pragma unroll
        for (int n = 0; n < 8; n++) {
            int r = m0 + m * 16 + (lane >> 2);
            int c = n0 + n * 8 + (lane & 3) * 2;
            Cb[r * 129 + c]           = acc[m][n][0];
            Cb[r * 129 + c + 1]       = acc[m][n][1];
            Cb[(r + 8) * 129 + c]     = acc[m][n][2];
            Cb[(r + 8) * 129 + c + 1] = acc[m][n][3];
        }
}

// ---------------- pre-pass kernels ----------------
__global__ void conv_w_kernel(const float* __restrict__ w) {
    int i4 = blockIdx.x * 256 + threadIdx.x;
    float4 v = reinterpret_cast<const float4*>(w)[i4];
    __nv_bfloat16 h0, l0, h1, l1, h2, l2, h3, l3;
    split2(v.x, h0, l0); split2(v.y, h1, l1); split2(v.z, h2, l2); split2(v.w, h3, l3);
    reinterpret_cast<uint2*>(g_w_hi)[i4] = make_uint2(pack_bf2(h0, h1), pack_bf2(h2, h3));
    reinterpret_cast<uint2*>(g_w_lo)[i4] = make_uint2(pack_bf2(l0, l1), pack_bf2(l2, l3));
}

__global__ void trans_tgt_kernel(const float* __restrict__ in) {   // [b][i][q]->[b][q][i]
    __shared__ float t[32][33];
    int b = blockIdx.z, i0 = blockIdx.y * 32, q0 = blockIdx.x * 32;
    int x = threadIdx.x, y = threadIdx.y;
#pragma unroll
    for (int r = 0; r < 32; r += 8)
        t[y + r][x] = in[((size_t)b * IDF + i0 + y + r) * QL + q0 + x];
    __syncthreads();
#pragma unroll
    for (int r = 0; r < 32; r += 8) {
        size_t o = ((size_t)b * QL + q0 + y + r) * IDF + i0 + x;
        __nv_bfloat16 h, l; split2(t[x][y + r], h, l);
        g_tgtT_hi[o] = h; g_tgtT_lo[o] = l;
    }
}

__global__ void trans_ctx_kernel(const float* __restrict__ in) {   // [b][c][s]->[b][s][c]
    __shared__ float t[32][33];
    int b = blockIdx.z, c0 = blockIdx.y * 32, s0 = blockIdx.x * 32;
    int x = threadIdx.x, y = threadIdx.y;
#pragma unroll
    for (int r = 0; r < 32; r += 8)
        t[y + r][x] = in[((size_t)b * CDF + c0 + y + r) * SL + s0 + x];
    __syncthreads();
#pragma unroll
    for (int r = 0; r < 32; r += 8) {
        size_t o = ((size_t)b * SL + s0 + y + r) * CDF + c0 + x;
        __nv_bfloat16 h, l; split2(t[x][y + r], h, l);
        g_ctxT_hi[o] = h; g_ctxT_lo[o] = l;
    }
}

// ---------------- proj: srcT = W @ ctx, writes [i][s] and [s][i] splits ----------------
__global__ void __launch_bounds__(256, 1) proj_kernel() {
    extern __shared__ __align__(128) char smem[];
    const int tid = threadIdx.x, lane = tid & 31, wp = tid >> 5;
    const int wm = wp & 3, wn = wp >> 2;
    const int b = blockIdx.y, o0 = blockIdx.x * 128;
    uint32_t sb = smem_u32(smem);
    const uint32_t AHI = sb, ALO = sb + 16384, BHI = sb + 32768, BLO = sb + 49152;
    float* Cb = reinterpret_cast<float*>(smem + 65536);

    float acc[2][8][4];
#pragma unroll
    for (int m = 0; m < 2; m++)
#pragma unroll
        for (int n = 0; n < 8; n++)
#pragma unroll
            for (int v = 0; v < 4; v++) acc[m][n][v] = 0.f;

    for (int j = 0; j < 12; j++) {
        if (j) __syncthreads();
        cp_tile(AHI, g_w_hi + (size_t)o0 * CDF + j * 64, CDF * 2, tid);
        cp_tile(ALO, g_w_lo + (size_t)o0 * CDF + j * 64, CDF * 2, tid);
        cp_tile(BHI, g_ctxT_hi + ((size_t)b * SL) * CDF + j * 64, CDF * 2, tid);
        cp_tile(BLO, g_ctxT_lo + ((size_t)b * SL) * CDF + j * 64, CDF * 2, tid);
        __syncthreads();
#pragma unroll 1
        for (int k = 0; k < 4; k++)
            gemm_k16(acc, AHI, ALO, BHI, BLO, k * 32, wm * 32, wn * 64, lane);
    }
    frag_to_cbuf(Cb, acc, wm * 32, wn * 64, lane);
    __syncthreads();

    const int r = tid >> 1, h = tid & 1;
    // sis [i][s]: row o = r, s in [h*64, h*64+64)
#pragma unroll
    for (int c0 = 0; c0 < 64; c0 += 32) {
        uint32_t uh[16], ul[16];
#pragma unroll
        for (int m = 0; m < 16; m++) {
            float v0 = Cb[r * 129 + h * 64 + c0 + 2 * m];
            float v1 = Cb[r * 129 + h * 64 + c0 + 2 * m + 1];
            __nv_bfloat16 h0, l0, h1, l1; split2(v0, h0, l0); split2(v1, h1, l1);
            uh[m] = pack_bf2(h0, h1); ul[m] = pack_bf2(l0, l1);
        }
        size_t off = ((size_t)b * IDF + o0 + r) * SL + h * 64 + c0;
#pragma unroll
        for (int m = 0; m < 4; m++) {
            reinterpret_cast<uint4*>(g_sis_hi + off)[m] =
                make_uint4(uh[4 * m], uh[4 * m + 1], uh[4 * m + 2], uh[4 * m + 3]);
            reinterpret_cast<uint4*>(g_sis_lo + off)[m] =
                make_uint4(ul[4 * m], ul[4 * m + 1], ul[4 * m + 2], ul[4 * m + 3]);
        }
    }
    // ssi [s][i]: s = r, i in [h*64, h*64+64)
#pragma unroll
    for (int c0 = 0; c0 < 64; c0 += 32) {
        uint32_t uh[16], ul[16];
#pragma unroll
        for (int m = 0; m < 16; m++) {
            float v0 = Cb[(h * 64 + c0 + 2 * m) * 129 + r];
            float v1 = Cb[(h * 64 + c0 + 2 * m + 1) * 129 + r];
            __nv_bfloat16 h0, l0, h1, l1; split2(v0, h0, l0); split2(v1, h1, l1);
            uh[m] = pack_bf2(h0, h1); ul[m] = pack_bf2(l0, l1);
        }
        size_t off = ((size_t)b * SL + r) * IDF + o0 + h * 64 + c0;
#pragma unroll
        for (int m = 0; m < 4; m++) {
            reinterpret_cast<uint4*>(g_ssi_hi + off)[m] =
                make_uint4(uh[4 * m], uh[4 * m + 1], uh[4 * m + 2], uh[4 * m + 3]);
            reinterpret_cast<uint4*>(g_ssi_lo + off)[m] =
                make_uint4(ul[4 * m], ul[4 * m + 1], ul[4 * m + 2], ul[4 * m + 3]);
        }
    }
}

// ---------------- fused attention ----------------
__global__ void __launch_bounds__(256, 1) attn_kernel(const int* __restrict__ mask,
                                                      float* __restrict__ wc,
                                                      float* __restrict__ aout) {
    extern __shared__ __align__(128) char smem[];
    __shared__ float mpen[SL];
    const int tid = threadIdx.x, lane = tid & 31, wp = tid >> 5;
    const int wm = wp & 3, wn = wp >> 2;
    const int b = blockIdx.y, q0 = blockIdx.x * 128;
    uint32_t sb = smem_u32(smem);
    const uint32_t STG = sb;               // 64KB staging (4 x 16KB sub-tiles)
    const uint32_t BATT = sb + 65536;      // attn bf16: hi(s0),hi(s1),lo(s0),lo(s1)
    float* Cb = reinterpret_cast<float*>(smem + 131072);

    if (tid < SL) mpen[tid] = -10000.0f * (float)mask[b * SL + tid];

    float acc[2][8][4];
#pragma unroll
    for (int m = 0; m < 2; m++)
#pragma unroll
        for (int n = 0; n < 8; n++)
#pragma unroll
            for (int v = 0; v < 4; v++) acc[m][n][v] = 0.f;

    // phase 1: logits[q][s], K=768
    for (int j = 0; j < 12; j++) {
        if (j) __syncthreads();
        cp_tile(STG,         g_tgtT_hi + ((size_t)b * QL + q0) * IDF + j * 64, IDF * 2, tid);
        cp_tile(STG + 16384, g_tgtT_lo + ((size_t)b * QL + q0) * IDF + j * 64, IDF * 2, tid);
        cp_tile(STG + 32768, g_ssi_hi + ((size_t)b * SL) * IDF + j * 64, IDF * 2, tid);
        cp_tile(STG + 49152, g_ssi_lo + ((size_t)b * SL) * IDF + j * 64, IDF * 2, tid);
        __syncthreads();
#pragma unroll 1
        for (int k = 0; k < 4; k++)
            gemm_k16(acc, STG, STG + 16384, STG + 32768, STG + 49152,
                     k * 32, wm * 32, wn * 64, lane);
    }
    frag_to_cbuf(Cb, acc, wm * 32, wn * 64, lane);
    __syncthreads();

    // phase 2: softmax over s; write normalized fp32 to Cb + bf16 split to BATT
    {
        const int q = tid >> 1, h = tid & 1;
        float* row = Cb + q * 129 + h * 64;
        float mx = -1e30f;
#pragma unroll
        for (int s = 0; s < 64; s++) {
            float x = row[s] + mpen[h * 64 + s];
            row[s] = x;
            mx = fmaxf(mx, x);
        }
        mx = fmaxf(mx, __shfl_xor_sync(0xffffffffu, mx, 1));
        float sum = 0.f;
#pragma unroll
        for (int s = 0; s < 64; s++) {
            float e = __expf(row[s] - mx);
            row[s] = e;
            sum += e;
        }
        sum += __shfl_xor_sync(0xffffffffu, sum, 1);
        float inv = 1.0f / sum;
        uint32_t BH = BATT + h * 16384;
        uint32_t BL = BATT + 32768 + h * 16384;
#pragma unroll
        for (int s = 0; s < 64; s += 2) {
            float a0 = row[s] * inv, a1 = row[s + 1] * inv;
            row[s] = a0; row[s + 1] = a1;
            __nv_bfloat16 h0, l0, h1, l1; split2(a0, h0, l0); split2(a1, h1, l1);
            uint32_t off = SW128((uint32_t)(q * 128 + s * 2));
            asm volatile("st.shared.b32 [%0], %1;" :: "r"(BH + off), "r"(pack_bf2(h0, h1)));
            asm volatile("st.shared.b32 [%0], %1;" :: "r"(BL + off), "r"(pack_bf2(l0, l1)));
        }
    }
    __syncthreads();

    // attn_out [b][s][q]
    {
        float* ao = aout + (size_t)b * SL * QL + q0;
        const int qc = tid & 127;
#pragma unroll 4
        for (int s2 = 0; s2 < 128; s2 += 2) {
            int s = s2 + (tid >> 7);
            ao[(size_t)s * QL + qc] = Cb[qc * 129 + s];
        }
    }

    // phase 3: wc[i][q] = sum_s sis[i][s]*attn[q][s], 6 i-tiles, K=128
    for (int t = 0; t < 6; t++) {
        __syncthreads();
        const size_t base = ((size_t)b * IDF + t * 128) * SL;
        cp_tile(STG,         g_sis_hi + base,      SL * 2, tid);
        cp_tile(STG + 16384, g_sis_hi + base + 64, SL * 2, tid);
        cp_tile(STG + 32768, g_sis_lo + base,      SL * 2, tid);
        cp_tile(STG + 49152, g_sis_lo + base + 64, SL * 2, tid);
        __syncthreads();
        float a3[2][8][4];
#pragma unroll
        for (int m = 0; m < 2; m++)
#pragma unroll
            for (int n = 0; n < 8; n++)
#pragma unroll
                for (int v = 0; v < 4; v++) a3[m][n][v] = 0.f;
#pragma unroll 1
        for (int kc = 0; kc < 8; kc++) {
            int hf = kc >> 2, kb = (kc & 3) * 32;
            gemm_k16(a3, STG + hf * 16384, STG + 32768 + hf * 16384,
                     BATT + hf * 16384, BATT + 32768 + hf * 16384,
                     kb, wm * 32, wn * 64, lane);
        }
        float* w0 = wc + ((size_t)b * IDF + t * 128) * QL + q0;
#pragma unroll
        for (int m = 0; m < 2; m++)
#pragma unroll
            for (int n = 0; n < 8; n++) {
                int r = wm * 32 + m * 16 + (lane >> 2);
                int c = wn * 64 + n * 8 + (lane & 3) * 2;
                *reinterpret_cast<float2*>(w0 + (size_t)r * QL + c) =
                    make_float2(a3[m][n][0], a3[m][n][1]);
                *reinterpret_cast<float2*>(w0 + (size_t)(r + 8) * QL + c) =
                    make_float2(a3[m][n][2], a3[m][n][3]);
            }
    }
}

// ---------------------------------------------------------------------------
extern "C" void kernel_launch(void* const* d_in, const int* in_sizes, int n_in,
                              void* d_out, int out_size) {
    const float* input   = (const float*)d_in[0];
    const float* context = (const float*)d_in[1];
    const int*   mask    = (const int*)d_in[2];
    const float* w_conv  = (const float*)d_in[3];

    float* wc   = (float*)d_out;
    float* aout = wc + (size_t)NB * IDF * QL;

    conv_w_kernel<<<IDF * CDF / 4 / 256, 256>>>(w_conv);
    trans_tgt_kernel<<<dim3(QL / 32, IDF / 32, NB), dim3(32, 8)>>>(input);
    trans_ctx_kernel<<<dim3(SL / 32, CDF / 32, NB), dim3(32, 8)>>>(context);

    const int smem_proj = 65536 + 128 * 129 * 4;
    cudaFuncSetAttribute(proj_kernel, cudaFuncAttributeMaxDynamicSharedMemorySize, smem_proj);
    proj_kernel<<<dim3(IDF / 128, NB), 256, smem_proj>>>();

    const int smem_attn = 131072 + 128 * 129 * 4;
    cudaFuncSetAttribute(attn_kernel, cudaFuncAttributeMaxDynamicSharedMemorySize, smem_attn);
    attn_kernel<<<dim3(QL / 128, NB), 256, smem_attn>>>(mask, wc, aout);
}

// round 5
// speedup vs baseline: 2.4357x; 1.3444x over previous
#include <cuda_runtime.h>
#include <cuda_bf16.h>
#include <stdint.h>

#define NB  32
#define IDF 768
#define CDF 768
#define QL  1024
#define SL  128

__device__ __align__(128) __nv_bfloat16 g_w_hi[(size_t)IDF * CDF];
__device__ __align__(128) __nv_bfloat16 g_w_lo[(size_t)IDF * CDF];
__device__ __align__(128) __nv_bfloat16 g_ctxT_hi[(size_t)NB * SL * CDF];
__device__ __align__(128) __nv_bfloat16 g_ctxT_lo[(size_t)NB * SL * CDF];
__device__ __align__(128) __nv_bfloat16 g_sis_hi[(size_t)NB * IDF * SL];   // [b][i][s]
__device__ __align__(128) __nv_bfloat16 g_sis_lo[(size_t)NB * IDF * SL];
__device__ __align__(128) __nv_bfloat16 g_ssi_hi[(size_t)NB * SL * IDF];   // [b][s][i]
__device__ __align__(128) __nv_bfloat16 g_ssi_lo[(size_t)NB * SL * IDF];

__device__ __forceinline__ uint32_t smem_u32(const void* p) {
    uint32_t a;
    asm("{ .reg .u64 t; cvta.to.shared.u64 t, %1; cvt.u32.u64 %0, t; }" : "=r"(a) : "l"(p));
    return a;
}
#define SW128(x) ((x) ^ (((x) >> 3) & 0x70))

__device__ __forceinline__ void split2(float v, __nv_bfloat16& h, __nv_bfloat16& l) {
    h = __float2bfloat16(v);
    l = __float2bfloat16(v - __bfloat162float(h));
}
__device__ __forceinline__ uint32_t pack_bf2(__nv_bfloat16 a, __nv_bfloat16 b) {
    __nv_bfloat162 p; p.x = a; p.y = b;
    return *reinterpret_cast<uint32_t*>(&p);
}

#define CP_A16(dst, src) \
    asm volatile("cp.async.cg.shared.global [%0], [%1], 16;" :: "r"(dst), "l"(src))
#define CP_COMMIT() asm volatile("cp.async.commit_group;" ::: "memory")
#define CP_WAIT0()  asm volatile("cp.async.wait_group 0;" ::: "memory")

// bf16 K-major [NROWS x 128B] tile, SW128-swizzled, via cp.async. gstride bytes.
template <int PASSES>   // PASSES = NROWS/32 (256 thr x 16B x PASSES)
__device__ __forceinline__ void cp_tile_async(uint32_t sbase, const __nv_bfloat16* g,
                                              int gstride, int tid) {
#pragma unroll
    for (int p = 0; p < PASSES; p++) {
        int idx = tid + p * 256;
        int row = idx >> 3;
        int c   = (idx & 7) << 4;
        const char* src = reinterpret_cast<const char*>(g) + (size_t)row * gstride + c;
        CP_A16(sbase + SW128((uint32_t)(row * 128 + c)), src);
    }
}

// x4 ldmatrix of a 16x16 bf16 block at (row0, kbyte) in a SW128 [r][128B] tile.
__device__ __forceinline__ void ldm4(uint32_t r[4], uint32_t base, int row0,
                                     int kbyte, int lane) {
    int row = row0 + (lane & 15);
    int col = kbyte + ((lane >> 4) << 4);
    uint32_t addr = base + SW128((uint32_t)(row * 128 + col));
    asm volatile("ldmatrix.sync.aligned.m8n8.x4.shared.b16 {%0,%1,%2,%3}, [%4];"
                 : "=r"(r[0]), "=r"(r[1]), "=r"(r[2]), "=r"(r[3]) : "r"(addr));
}

__device__ __forceinline__ void mma16(float c[4], const uint32_t a[4], const uint32_t b[2]) {
    asm volatile("mma.sync.aligned.m16n8k16.row.col.f32.bf16.bf16.f32 "
                 "{%0,%1,%2,%3}, {%4,%5,%6,%7}, {%8,%9}, {%0,%1,%2,%3};"
                 : "+f"(c[0]), "+f"(c[1]), "+f"(c[2]), "+f"(c[3])
                 : "r"(a[0]), "r"(a[1]), "r"(a[2]), "r"(a[3]), "r"(b[0]), "r"(b[1]));
}

// One k16 step of a 32(m) x 32(n) warp tile, split-bf16 (3 mmas per pair).
__device__ __forceinline__ void gemm32(float acc[2][4][4],
                                       uint32_t aHi, uint32_t aLo,
                                       uint32_t bHi, uint32_t bLo,
                                       int kbyte, int m0, int n0, int lane) {
    uint32_t ah[2][4], al[2][4], bh[4][2], bl[4][2], t[4];
#pragma unroll
    for (int m = 0; m < 2; m++) {
        ldm4(ah[m], aHi, m0 + m * 16, kbyte, lane);
        ldm4(al[m], aLo, m0 + m * 16, kbyte, lane);
    }
#pragma unroll
    for (int j = 0; j < 2; j++) {
        ldm4(t, bHi, n0 + j * 16, kbyte, lane);
        bh[2 * j][0] = t[0]; bh[2 * j][1] = t[2];
        bh[2 * j + 1][0] = t[1]; bh[2 * j + 1][1] = t[3];
        ldm4(t, bLo, n0 + j * 16, kbyte, lane);
        bl[2 * j][0] = t[0]; bl[2 * j][1] = t[2];
        bl[2 * j + 1][0] = t[1]; bl[2 * j + 1][1] = t[3];
    }
#pragma unroll
    for (int m = 0; m < 2; m++)
#pragma unroll
        for (int n = 0; n < 4; n++) {
            mma16(acc[m][n], ah[m], bh[n]);
            mma16(acc[m][n], ah[m], bl[n]);
            mma16(acc[m][n], al[m], bh[n]);
        }
}

__device__ __forceinline__ void frag_to_cbuf(float* Cb, const float acc[2][4][4],
                                             int m0, int n0, int lane) {
#pragma unroll
    for (int m = 0; m < 2; m++)
#pragma unroll
        for (int n = 0; n < 4; n++) {
            int r = m0 + m * 16 + (lane >> 2);
            int c = n0 + n * 8 + (lane & 3) * 2;
            Cb[r * 129 + c]           = acc[m][n][0];
            Cb[r * 129 + c + 1]       = acc[m][n][1];
            Cb[(r + 8) * 129 + c]     = acc[m][n][2];
            Cb[(r + 8) * 129 + c + 1] = acc[m][n][3];
        }
}

// ---------------- pre-pass ----------------
__global__ void conv_w_kernel(const float* __restrict__ w) {
    int i4 = blockIdx.x * 256 + threadIdx.x;
    float4 v = reinterpret_cast<const float4*>(w)[i4];
    __nv_bfloat16 h0, l0, h1, l1, h2, l2, h3, l3;
    split2(v.x, h0, l0); split2(v.y, h1, l1); split2(v.z, h2, l2); split2(v.w, h3, l3);
    reinterpret_cast<uint2*>(g_w_hi)[i4] = make_uint2(pack_bf2(h0, h1), pack_bf2(h2, h3));
    reinterpret_cast<uint2*>(g_w_lo)[i4] = make_uint2(pack_bf2(l0, l1), pack_bf2(l2, l3));
}

__global__ void trans_ctx_kernel(const float* __restrict__ in) {   // [b][c][s]->[b][s][c]
    __shared__ float t[32][33];
    int b = blockIdx.z, c0 = blockIdx.y * 32, s0 = blockIdx.x * 32;
    int x = threadIdx.x, y = threadIdx.y;
#pragma unroll
    for (int r = 0; r < 32; r += 8)
        t[y + r][x] = in[((size_t)b * CDF + c0 + y + r) * SL + s0 + x];
    __syncthreads();
#pragma unroll
    for (int r = 0; r < 32; r += 8) {
        size_t o = ((size_t)b * SL + s0 + y + r) * CDF + c0 + x;
        __nv_bfloat16 h, l; split2(t[x][y + r], h, l);
        g_ctxT_hi[o] = h; g_ctxT_lo[o] = l;
    }
}

// ---------------- proj: srcT[b,o,s] = sum_c w[o,c]*ctx[b,c,s] ----------------
// o-tile 64, grid (12, 32), 2 CTAs/SM. smem: staging 48KB (Cb 33KB aliased).
__global__ void __launch_bounds__(256, 2) proj_kernel() {
    extern __shared__ __align__(128) char smem[];
    const int tid = threadIdx.x, lane = tid & 31, wp = tid >> 5;
    const int wm = wp & 1, wn = wp >> 1;      // D tile 64(o) x 128(s)
    const int b = blockIdx.y, o0 = blockIdx.x * 64;
    uint32_t sb = smem_u32(smem);
    const uint32_t AHI = sb, ALO = sb + 8192, BHI = sb + 16384, BLO = sb + 32768;
    float* Cb = reinterpret_cast<float*>(smem);

    float acc[2][4][4];
#pragma unroll
    for (int m = 0; m < 2; m++)
#pragma unroll
        for (int n = 0; n < 4; n++)
#pragma unroll
            for (int v = 0; v < 4; v++) acc[m][n][v] = 0.f;

    for (int j = 0; j < 12; j++) {
        __syncthreads();
        cp_tile_async<2>(AHI, g_w_hi + (size_t)o0 * CDF + j * 64, CDF * 2, tid);
        cp_tile_async<2>(ALO, g_w_lo + (size_t)o0 * CDF + j * 64, CDF * 2, tid);
        cp_tile_async<4>(BHI, g_ctxT_hi + (size_t)b * SL * CDF + j * 64, CDF * 2, tid);
        cp_tile_async<4>(BLO, g_ctxT_lo + (size_t)b * SL * CDF + j * 64, CDF * 2, tid);
        CP_COMMIT();
        CP_WAIT0();
        __syncthreads();
#pragma unroll 1
        for (int k = 0; k < 4; k++)
            gemm32(acc, AHI, ALO, BHI, BLO, k * 32, wm * 32, wn * 32, lane);
    }
    __syncthreads();
    frag_to_cbuf(Cb, acc, wm * 32, wn * 32, lane);
    __syncthreads();

    // sis [b][i][s]: thread -> (o = tid/4, 32 s)
    {
        const int o = tid >> 2, sq = (tid & 3) * 32;
        uint32_t uh[16], ul[16];
#pragma unroll
        for (int m = 0; m < 16; m++) {
            float v0 = Cb[o * 129 + sq + 2 * m];
            float v1 = Cb[o * 129 + sq + 2 * m + 1];
            __nv_bfloat16 h0, l0, h1, l1; split2(v0, h0, l0); split2(v1, h1, l1);
            uh[m] = pack_bf2(h0, h1); ul[m] = pack_bf2(l0, l1);
        }
        size_t off = ((size_t)b * IDF + o0 + o) * SL + sq;
#pragma unroll
        for (int m = 0; m < 4; m++) {
            reinterpret_cast<uint4*>(g_sis_hi + off)[m] =
                make_uint4(uh[4 * m], uh[4 * m + 1], uh[4 * m + 2], uh[4 * m + 3]);
            reinterpret_cast<uint4*>(g_sis_lo + off)[m] =
                make_uint4(ul[4 * m], ul[4 * m + 1], ul[4 * m + 2], ul[4 * m + 3]);
        }
    }
    // ssi [b][s][i]: thread -> (s = tid/2, 32 o)
    {
        const int s = tid >> 1, oq = (tid & 1) * 32;
        uint32_t uh[16], ul[16];
#pragma unroll
        for (int m = 0; m < 16; m++) {
            float v0 = Cb[(oq + 2 * m) * 129 + s];
            float v1 = Cb[(oq + 2 * m + 1) * 129 + s];
            __nv_bfloat16 h0, l0, h1, l1; split2(v0, h0, l0); split2(v1, h1, l1);
            uh[m] = pack_bf2(h0, h1); ul[m] = pack_bf2(l0, l1);
        }
        size_t off = ((size_t)b * SL + s) * IDF + o0 + oq;
#pragma unroll
        for (int m = 0; m < 4; m++) {
            reinterpret_cast<uint4*>(g_ssi_hi + off)[m] =
                make_uint4(uh[4 * m], uh[4 * m + 1], uh[4 * m + 2], uh[4 * m + 3]);
            reinterpret_cast<uint4*>(g_ssi_lo + off)[m] =
                make_uint4(ul[4 * m], ul[4 * m + 1], ul[4 * m + 2], ul[4 * m + 3]);
        }
    }
}

// ---------------- fused attention: q-tile 64, grid (16, 32), 2 CTAs/SM ----------------
// smem: [0,49152) staging / Cb(33KB) union; [49152,81920) attn bf16 tiles.
__global__ void __launch_bounds__(256, 2) attn_kernel(const float* __restrict__ input,
                                                      const int* __restrict__ mask,
                                                      float* __restrict__ wc,
                                                      float* __restrict__ aout) {
    extern __shared__ __align__(128) char smem[];
    __shared__ float mpen[SL];
    const int tid = threadIdx.x, lane = tid & 31, wp = tid >> 5;
    const int b = blockIdx.y, q0 = blockIdx.x * 64;
    uint32_t sb = smem_u32(smem);
    const uint32_t AHI = sb, ALO = sb + 8192, BHI = sb + 16384, BLO = sb + 32768;
    const uint32_t SISH = sb, SISL = sb + 16384;          // phase-3 staging
    const uint32_t BATT = sb + 49152;                      // hi0,hi1,lo0,lo1 (8KB each)
    float* Cb = reinterpret_cast<float*>(smem);

    if (tid < SL) mpen[tid] = -10000.0f * (float)mask[b * SL + tid];

    // ---- phase 1: logits[q][s], K=768, 12 chunks of k=64 ----
    const int wm1 = wp & 1, wn1 = wp >> 1;    // D 64(q) x 128(s)
    float acc[2][4][4];
#pragma unroll
    for (int m = 0; m < 2; m++)
#pragma unroll
        for (int n = 0; n < 4; n++)
#pragma unroll
            for (int v = 0; v < 4; v++) acc[m][n][v] = 0.f;

    for (int j = 0; j < 12; j++) {
        __syncthreads();
        cp_tile_async<4>(BHI, g_ssi_hi + (size_t)b * SL * IDF + j * 64, IDF * 2, tid);
        cp_tile_async<4>(BLO, g_ssi_lo + (size_t)b * SL * IDF + j * 64, IDF * 2, tid);
        CP_COMMIT();
        // A: convert input[b][i][q] -> bf16 split tiles [q][i] (k-major, SW128)
        {
            const int q = tid & 63, sec = tid >> 6;       // sec: 16 i-rows each
            const float* src = input + ((size_t)b * IDF + j * 64 + sec * 16) * QL + q0 + q;
            const uint32_t rowb = (uint32_t)(q * 128);
#pragma unroll
            for (int m = 0; m < 8; m++) {
                float v0 = src[(2 * m) * QL];
                float v1 = src[(2 * m + 1) * QL];
                __nv_bfloat16 h0, l0, h1, l1; split2(v0, h0, l0); split2(v1, h1, l1);
                uint32_t off = SW128(rowb + (uint32_t)(sec * 32 + 4 * m));
                asm volatile("st.shared.b32 [%0], %1;" :: "r"(AHI + off), "r"(pack_bf2(h0, h1)));
                asm volatile("st.shared.b32 [%0], %1;" :: "r"(ALO + off), "r"(pack_bf2(l0, l1)));
            }
        }
        CP_WAIT0();
        __syncthreads();
#pragma unroll 1
        for (int k = 0; k < 4; k++)
            gemm32(acc, AHI, ALO, BHI, BLO, k * 32, wm1 * 32, wn1 * 32, lane);
    }
    __syncthreads();
    frag_to_cbuf(Cb, acc, wm1 * 32, wn1 * 32, lane);
    __syncthreads();

    // ---- phase 2: softmax over s (4 threads per q-row) + BATT split ----
    {
        const int q = tid >> 2, qa = tid & 3;
        float* row = Cb + q * 129 + qa * 32;
        const float* mp = mpen + qa * 32;
        float mx = -1e30f;
#pragma unroll
        for (int s = 0; s < 32; s++) {
            float x = row[s] + mp[s];
            row[s] = x;
            mx = fmaxf(mx, x);
        }
        mx = fmaxf(mx, __shfl_xor_sync(0xffffffffu, mx, 1));
        mx = fmaxf(mx, __shfl_xor_sync(0xffffffffu, mx, 2));
        float sum = 0.f;
#pragma unroll
        for (int s = 0; s < 32; s++) {
            float e = __expf(row[s] - mx);
            row[s] = e;
            sum += e;
        }
        sum += __shfl_xor_sync(0xffffffffu, sum, 1);
        sum += __shfl_xor_sync(0xffffffffu, sum, 2);
        const float inv = 1.0f / sum;
        const int half = qa >> 1;                          // s-half (0: s<64)
        const uint32_t BH = BATT + half * 8192;
        const uint32_t BL = BATT + 16384 + half * 8192;
        const int sbase = (qa & 1) * 32;                   // within half
#pragma unroll
        for (int s = 0; s < 32; s += 2) {
            float a0 = row[s] * inv, a1 = row[s + 1] * inv;
            row[s] = a0; row[s + 1] = a1;
            __nv_bfloat16 h0, l0, h1, l1; split2(a0, h0, l0); split2(a1, h1, l1);
            uint32_t off = SW128((uint32_t)(q * 128 + (sbase + s) * 2));
            asm volatile("st.shared.b32 [%0], %1;" :: "r"(BH + off), "r"(pack_bf2(h0, h1)));
            asm volatile("st.shared.b32 [%0], %1;" :: "r"(BL + off), "r"(pack_bf2(l0, l1)));
        }
    }
    __syncthreads();

    // attn_out[b][s][q0+q]
    {
        float* ao = aout + (size_t)b * SL * QL + q0;
        const int q = tid & 63;
#pragma unroll 4
        for (int it = 0; it < 32; it++) {
            int s = it * 4 + (tid >> 6);
            ao[(size_t)s * QL + q] = Cb[q * 129 + s];
        }
    }

    // ---- phase 3: wc[i][q] = sum_s sis[i][s]*attn[q][s], 6 i-tiles of 128 ----
    const int wm3 = wp >> 1, wn3 = wp & 1;    // D 128(i) x 64(q)
    for (int t2 = 0; t2 < 6; t2++) {
        float a3[2][4][4];
#pragma unroll
        for (int m = 0; m < 2; m++)
#pragma unroll
            for (int n = 0; n < 4; n++)
#pragma unroll
                for (int v = 0; v < 4; v++) a3[m][n][v] = 0.f;
#pragma unroll 1
        for (int hf = 0; hf < 2; hf++) {
            __syncthreads();
            const size_t base = ((size_t)b * IDF + t2 * 128) * SL + hf * 64;
            cp_tile_async<4>(SISH, g_sis_hi + base, SL * 2, tid);
            cp_tile_async<4>(SISL, g_sis_lo + base, SL * 2, tid);
            CP_COMMIT();
            CP_WAIT0();
            __syncthreads();
#pragma unroll 1
            for (int k = 0; k < 4; k++)
                gemm32(a3, SISH, SISL, BATT + hf * 8192, BATT + 16384 + hf * 8192,
                       k * 32, wm3 * 32, wn3 * 32, lane);
        }
        float* w0 = wc + ((size_t)b * IDF + t2 * 128) * QL + q0;
#pragma unroll
        for (int m = 0; m < 2; m++)
#pragma unroll
            for (int n = 0; n < 4; n++) {
                int r = wm3 * 32 + m * 16 + (lane >> 2);
                int c = wn3 * 32 + n * 8 + (lane & 3) * 2;
                *reinterpret_cast<float2*>(w0 + (size_t)r * QL + c) =
                    make_float2(a3[m][n][0], a3[m][n][1]);
                *reinterpret_cast<float2*>(w0 + (size_t)(r + 8) * QL + c) =
                    make_float2(a3[m][n][2], a3[m][n][3]);
            }
    }
}

// ---------------------------------------------------------------------------
extern "C" void kernel_launch(void* const* d_in, const int* in_sizes, int n_in,
                              void* d_out, int out_size) {
    const float* input   = (const float*)d_in[0];
    const float* context = (const float*)d_in[1];
    const int*   mask    = (const int*)d_in[2];
    const float* w_conv  = (const float*)d_in[3];

    float* wc   = (float*)d_out;
    float* aout = wc + (size_t)NB * IDF * QL;

    conv_w_kernel<<<IDF * CDF / 4 / 256, 256>>>(w_conv);
    trans_ctx_kernel<<<dim3(SL / 32, CDF / 32, NB), dim3(32, 8)>>>(context);

    const int smem_proj = 49152;
    cudaFuncSetAttribute(proj_kernel, cudaFuncAttributeMaxDynamicSharedMemorySize, smem_proj);
    proj_kernel<<<dim3(IDF / 64, NB), 256, smem_proj>>>();

    const int smem_attn = 81920;
    cudaFuncSetAttribute(attn_kernel, cudaFuncAttributeMaxDynamicSharedMemorySize, smem_attn);
    attn_kernel<<<dim3(QL / 64, NB), 256, smem_attn>>>(input, mask, wc, aout);
}